// round 15
// baseline (speedup 1.0000x reference)
#include <cuda_runtime.h>
#include <cuda_bf16.h>
#include <cuda_fp16.h>
#include <cstdint>

#define EMAX  4000000
#define NMAX  250000
#define DIM   64
// padded CSR capacity: E + 3 per row, rounded up
#define EPADMAX (EMAX + 3 * NMAX + 64)

// ---------------- device scratch (zero-initialized at load; trailing
// cleanup kernel restores zeros for the next graph replay) ------------------
__device__ int   g_cnt[NMAX];          // per-row real-edge count
__device__ int   g_rowptr[NMAX];       // padded excl. prefix; scatter advances
__device__ float g_dinv[NMAX];         // rsqrt(deg) incl. self loop
__device__ unsigned long long g_desc[512];  // lookback descriptors
__device__ int   g_ecol[EPADMAX];      // padded CSR cols (dummy = n)
__device__ uint4 g_xa[(size_t)(NMAX + 1) * 8]; // fp16 features ping; row n = 0
__device__ uint4 g_xb[(size_t)(NMAX + 1) * 8]; // fp16 features pong; row n = 0

#define FLAG_AGG    (1ULL << 62)
#define FLAG_PREFIX (2ULL << 62)
#define VAL_MASK    ((1ULL << 62) - 1)

// --- 1) degree histogram (4 edges/thread) + prefill padded CSR with dummy --
__global__ void k_count(const int* __restrict__ row, int E, int epad4, int dummy) {
    int t = blockIdx.x * blockDim.x + threadIdx.x;
    if (t < epad4)
        *(int4*)&g_ecol[t * 4] = make_int4(dummy, dummy, dummy, dummy);
    int e = t * 4;
    if (e + 3 < E) {
        int4 r4 = __ldg((const int4*)(row + e));
        atomicAdd(&g_cnt[r4.x], 1);
        atomicAdd(&g_cnt[r4.y], 1);
        atomicAdd(&g_cnt[r4.z], 1);
        atomicAdd(&g_cnt[r4.w], 1);
    } else {
        for (int i = e; i < E; i++) atomicAdd(&g_cnt[row[i]], 1);
    }
}

// --- 2) single-pass exclusive scan of PADDED counts + dinv + prescale ------
__global__ void __launch_bounds__(1024, 1) k_scan(const float* __restrict__ emb, int n) {
    __shared__ int s[1024];
    __shared__ int s_off;
    int b = blockIdx.x;
    int i = b * 1024 + threadIdx.x;
    int v  = (i < n) ? g_cnt[i] : 0;
    int pv = (v + 3) & ~3;                 // padded row length
    s[threadIdx.x] = pv;
    __syncthreads();
    #pragma unroll
    for (int off = 1; off < 1024; off <<= 1) {
        int x = (threadIdx.x >= off) ? s[threadIdx.x - off] : 0;
        __syncthreads();
        s[threadIdx.x] += x;
        __syncthreads();
    }
    if (threadIdx.x == 0) {
        unsigned long long total = (unsigned long long)s[1023];
        if (b == 0) {
            __threadfence();
            atomicExch(&g_desc[0], FLAG_PREFIX | total);
            s_off = 0;
        } else {
            __threadfence();
            atomicExch(&g_desc[b], FLAG_AGG | total);
            unsigned long long acc = 0;
            int j = b - 1;
            while (true) {
                unsigned long long d = atomicAdd(&g_desc[j], 0ULL);
                unsigned long long f = d >> 62;
                if (f == 2ULL) { acc += (d & VAL_MASK); break; }
                if (f == 1ULL) { acc += (d & VAL_MASK); j--; }
                else __nanosleep(20);
            }
            __threadfence();
            atomicExch(&g_desc[b], FLAG_PREFIX | (acc + total));
            s_off = (int)acc;
        }
    }
    __syncthreads();
    if (i < n) {
        g_rowptr[i] = s_off + s[threadIdx.x] - pv; // padded row start (4-aligned)
        g_dinv[i]   = rsqrtf((float)(v + 1));      // +1 self loop
    }
    // Fused prescale: x0 = fp16(dinv * emb); 16 threads/node, 4 floats each.
    __syncthreads();
    int node0 = b * 1024;
    uint2* xa2 = (uint2*)g_xa;
    for (int sweep = 0; sweep < 16; sweep++) {
        int node = node0 + sweep * 64 + (threadIdx.x >> 4);
        int q = threadIdx.x & 15;
        if (node < n) {
            float sc = g_dinv[node];
            float4 f = __ldg((const float4*)(emb + (size_t)node * DIM + q * 4));
            __half2 h0 = __floats2half2_rn(sc * f.x, sc * f.y);
            __half2 h1 = __floats2half2_rn(sc * f.z, sc * f.w);
            xa2[(size_t)node * 16 + q] = make_uint2(*(unsigned*)&h0, *(unsigned*)&h1);
        }
    }
}

// --- 3) counting-sort scatter: advances g_rowptr toward row end ------------
__global__ void k_scatter(const int* __restrict__ row, const int* __restrict__ col, int E) {
    int t = blockIdx.x * blockDim.x + threadIdx.x;
    int e = t * 4;
    if (e + 3 < E) {
        int4 r4 = __ldg((const int4*)(row + e));
        int4 c4 = __ldg((const int4*)(col + e));
        int p0 = atomicAdd(&g_rowptr[r4.x], 1);
        int p1 = atomicAdd(&g_rowptr[r4.y], 1);
        int p2 = atomicAdd(&g_rowptr[r4.z], 1);
        int p3 = atomicAdd(&g_rowptr[r4.w], 1);
        g_ecol[p0] = c4.x;
        g_ecol[p1] = c4.y;
        g_ecol[p2] = c4.z;
        g_ecol[p3] = c4.w;
    } else {
        for (int i = e; i < E; i++) {
            int p = atomicAdd(&g_rowptr[row[i]], 1);
            g_ecol[p] = col[i];
        }
    }
}

// --- streaming (evict-first) float4 store ----------------------------------
__device__ __forceinline__ void stcs_f4(float* p, float4 v) {
    asm volatile("st.global.cs.v4.f32 [%0], {%1, %2, %3, %4};"
                 :: "l"(p), "f"(v.x), "f"(v.y), "f"(v.z), "f"(v.w) : "memory");
}

// fp32 accumulate of a uint4 (8 fp16 values)
__device__ __forceinline__ void acc_u4(float4& a0, float4& a1, uint4 g) {
    float2 t;
    t = __half22float2(*(__half2*)&g.x); a0.x += t.x; a0.y += t.y;
    t = __half22float2(*(__half2*)&g.y); a0.z += t.x; a0.w += t.y;
    t = __half22float2(*(__half2*)&g.z); a1.x += t.x; a1.y += t.y;
    t = __half22float2(*(__half2*)&g.w); a1.z += t.x; a1.w += t.y;
}

// one-level fp16 pair add: r = a + b (componentwise half2)
__device__ __forceinline__ uint4 hadd_u4(uint4 a, uint4 b) {
    uint4 r;
    *(__half2*)&r.x = __hadd2(*(__half2*)&a.x, *(__half2*)&b.x);
    *(__half2*)&r.y = __hadd2(*(__half2*)&a.y, *(__half2*)&b.y);
    *(__half2*)&r.z = __hadd2(*(__half2*)&a.z, *(__half2*)&b.z);
    *(__half2*)&r.w = __hadd2(*(__half2*)&a.w, *(__half2*)&b.w);
    return r;
}

// --- 4) SpMM on padded CSR: 4 rows/warp, 8 lanes/row, 16B per lane ---------
// Branch-free inner loop. Per 4 edges: 1 int4 index LDG + 4 gathers +
// 8 HADD2 (pairwise fp16) + 8 CVT + 16 FADD (fp32 accumulate).
__global__ void __launch_bounds__(256) k_spmm(
        const uint4* __restrict__ gx,
        float* __restrict__ out,           // stride 192 (permuted slot)
        uint4* __restrict__ xnext,         // 8 uint4 per row, or nullptr
        float* __restrict__ dup,           // stride 64 fp32, or nullptr
        int n) {
    int warpId = (blockIdx.x * blockDim.x + threadIdx.x) >> 5;
    int lane = threadIdx.x & 31;
    int slot = lane >> 3;                  // 0..3: row slot within warp
    int sub  = lane & 7;                   // 0..7: cols [sub*8, sub*8+8)
    int r = warpId * 4 + slot;
    bool rowok = (r < n);
    int rr = rowok ? r : 0;

    const char* gbase = (const char*)gx + ((unsigned)sub << 4);

    float4 a0, a1;
    {
        uint4 u = __ldg((const uint4*)(gbase + ((unsigned)rr << 7)));  // x[r]
        float2 t;
        t = __half22float2(*(__half2*)&u.x); a0 = make_float4(t.x, t.y, 0.f, 0.f);
        t = __half22float2(*(__half2*)&u.y); a0.z = t.x; a0.w = t.y;
        t = __half22float2(*(__half2*)&u.z); a1 = make_float4(t.x, t.y, 0.f, 0.f);
        t = __half22float2(*(__half2*)&u.w); a1.z = t.x; a1.w = t.y;
    }

    int len   = rowok ? __ldg(&g_cnt[rr]) : 0;
    int pecur = rowok ? __ldg(&g_rowptr[rr]) : 0;  // = start + len (post-scatter)
    int p     = pecur - len;                        // padded start (4-aligned)
    int pend  = p + ((len + 3) & ~3);               // padded end

    for (; p < pend; p += 4) {
        int4 c = __ldg((const int4*)&g_ecol[p]);
        uint4 g0 = __ldg((const uint4*)(gbase + ((unsigned)c.x << 7)));
        uint4 g1 = __ldg((const uint4*)(gbase + ((unsigned)c.y << 7)));
        uint4 g2 = __ldg((const uint4*)(gbase + ((unsigned)c.z << 7)));
        uint4 g3 = __ldg((const uint4*)(gbase + ((unsigned)c.w << 7)));
        uint4 s01 = hadd_u4(g0, g1);       // one fp16 add per element
        uint4 s23 = hadd_u4(g2, g3);
        acc_u4(a0, a1, s01);               // fp32 accumulate
        acc_u4(a0, a1, s23);
    }

    if (rowok) {
        float s = __ldg(&g_dinv[r]);
        float4 o0 = make_float4(s * a0.x, s * a0.y, s * a0.z, s * a0.w);
        float4 o1 = make_float4(s * a1.x, s * a1.y, s * a1.z, s * a1.w);
        float* orow = out + (size_t)r * 192 + sub * 8;
        stcs_f4(orow, o0);
        stcs_f4(orow + 4, o1);
        if (xnext) {
            __half2 q0 = __floats2half2_rn(s * o0.x, s * o0.y);
            __half2 q1 = __floats2half2_rn(s * o0.z, s * o0.w);
            __half2 q2 = __floats2half2_rn(s * o1.x, s * o1.y);
            __half2 q3 = __floats2half2_rn(s * o1.z, s * o1.w);
            xnext[(size_t)r * 8 + sub] =
                make_uint4(*(unsigned*)&q0, *(unsigned*)&q1,
                           *(unsigned*)&q2, *(unsigned*)&q3);
        }
        if (dup) {
            float* drow = dup + (size_t)r * DIM + sub * 8;
            stcs_f4(drow, o0);
            stcs_f4(drow + 4, o1);
        }
    }
}

// --- 5) cleanup: restore zeros for the next graph replay -------------------
__global__ void k_cleanup(int n) {
    int i = blockIdx.x * blockDim.x + threadIdx.x;
    if (i < n) g_cnt[i] = 0;
    if (i < 512) g_desc[i] = 0ULL;
}

// ---------------------------------------------------------------------------
extern "C" void kernel_launch(void* const* d_in, const int* in_sizes, int n_in,
                              void* d_out, int out_size) {
    const int* edge_index = (const int*)d_in[0];
    const float* emb      = (const float*)d_in[1];

    const int E = in_sizes[0] / 2;     // edge_index is (2, E) row-major
    const int n = in_sizes[1] / DIM;   // number of nodes

    const int* row = edge_index;
    const int* col = edge_index + E;

    float* out = (float*)d_out;
    // LAYER_PERM = (2,0,1): [0:64)=feats[2], [64:128)=feats[0], [128:192)=feats[1];
    // then feat (== feats[2]) again contiguously at n*192 if out_size covers it.
    float* f1 = out + 64;    // stride 192
    float* f2 = out + 128;   // stride 192
    float* f3 = out + 0;     // stride 192
    bool want_dup = ((long long)out_size >= (long long)n * 256);
    float* dup = want_dup ? (out + (size_t)n * 192) : nullptr;

    const int B = 256;
    const int q4 = (E + 3) / 4;
    const int epad = E + 3 * n + 16;       // upper bound on padded CSR size
    const int epad4 = (epad + 3) / 4;
    const int cnt_grid = (epad4 > q4 ? epad4 : q4);

    uint4* xa; cudaGetSymbolAddress((void**)&xa, g_xa);
    uint4* xb; cudaGetSymbolAddress((void**)&xb, g_xb);

    // g_cnt / g_desc are zero at entry (BSS on first call, k_cleanup after).
    k_count<<<(cnt_grid + B - 1) / B, B>>>(row, E, epad4, n);  // 0
    k_scan<<<(n + 1023) / 1024, 1024>>>(emb, n);               // 1
    k_scatter<<<(q4 + B - 1) / B, B>>>(row, col, E);           // 2

    // SpMM: 4 rows/warp -> 32 rows per 256-thread block
    const int spmm_blocks = (n + 31) / 32;
    k_spmm<<<spmm_blocks, B>>>(xa, f1, xb, nullptr, n);        // 3: layer 1
    k_spmm<<<spmm_blocks, B>>>(xb, f2, xa, nullptr, n);        // 4: layer 2
    k_spmm<<<spmm_blocks, B>>>(xa, f3, nullptr, dup, n);       // 5: layer 3

    k_cleanup<<<(n + B - 1) / B, B>>>(n);                      // 6
}

// round 16
// speedup vs baseline: 1.0449x; 1.0449x over previous
#include <cuda_runtime.h>
#include <cuda_bf16.h>
#include <cuda_fp16.h>
#include <cstdint>

#define EMAX  4000000
#define NMAX  250000
#define DIM   64
// padded CSR capacity: E + 3 per row, rounded up
#define EPADMAX (EMAX + 3 * NMAX + 64)

// ---------------- device scratch (zero-initialized at load; trailing
// cleanup kernel restores zeros for the next graph replay) ------------------
__device__ int   g_cnt[NMAX];          // per-row real-edge count
__device__ int   g_rowptr[NMAX];       // padded excl. prefix; scatter advances
__device__ float g_dinv[NMAX];         // rsqrt(deg) incl. self loop
__device__ unsigned long long g_desc[512];  // lookback descriptors
__device__ int   g_ecol[EPADMAX];      // padded CSR cols (dummy = n)
__device__ uint4 g_xa[(size_t)(NMAX + 1) * 8]; // fp16 features ping; row n = 0
__device__ uint4 g_xb[(size_t)(NMAX + 1) * 8]; // fp16 features pong; row n = 0

#define FLAG_AGG    (1ULL << 62)
#define FLAG_PREFIX (2ULL << 62)
#define VAL_MASK    ((1ULL << 62) - 1)

// --- 1) degree histogram (4 edges/thread) + prefill padded CSR with dummy --
__global__ void k_count(const int* __restrict__ row, int E, int epad4, int dummy) {
    int t = blockIdx.x * blockDim.x + threadIdx.x;
    if (t < epad4)
        *(int4*)&g_ecol[t * 4] = make_int4(dummy, dummy, dummy, dummy);
    int e = t * 4;
    if (e + 3 < E) {
        int4 r4 = __ldg((const int4*)(row + e));
        atomicAdd(&g_cnt[r4.x], 1);
        atomicAdd(&g_cnt[r4.y], 1);
        atomicAdd(&g_cnt[r4.z], 1);
        atomicAdd(&g_cnt[r4.w], 1);
    } else {
        for (int i = e; i < E; i++) atomicAdd(&g_cnt[row[i]], 1);
    }
}

// --- 2) single-pass exclusive scan of PADDED counts + dinv + prescale ------
__global__ void __launch_bounds__(1024, 1) k_scan(const float* __restrict__ emb, int n) {
    __shared__ int s[1024];
    __shared__ int s_off;
    int b = blockIdx.x;
    int i = b * 1024 + threadIdx.x;
    int v  = (i < n) ? g_cnt[i] : 0;
    int pv = (v + 3) & ~3;                 // padded row length
    s[threadIdx.x] = pv;
    __syncthreads();
    #pragma unroll
    for (int off = 1; off < 1024; off <<= 1) {
        int x = (threadIdx.x >= off) ? s[threadIdx.x - off] : 0;
        __syncthreads();
        s[threadIdx.x] += x;
        __syncthreads();
    }
    if (threadIdx.x == 0) {
        unsigned long long total = (unsigned long long)s[1023];
        if (b == 0) {
            __threadfence();
            atomicExch(&g_desc[0], FLAG_PREFIX | total);
            s_off = 0;
        } else {
            __threadfence();
            atomicExch(&g_desc[b], FLAG_AGG | total);
            unsigned long long acc = 0;
            int j = b - 1;
            while (true) {
                unsigned long long d = atomicAdd(&g_desc[j], 0ULL);
                unsigned long long f = d >> 62;
                if (f == 2ULL) { acc += (d & VAL_MASK); break; }
                if (f == 1ULL) { acc += (d & VAL_MASK); j--; }
                else __nanosleep(20);
            }
            __threadfence();
            atomicExch(&g_desc[b], FLAG_PREFIX | (acc + total));
            s_off = (int)acc;
        }
    }
    __syncthreads();
    if (i < n) {
        g_rowptr[i] = s_off + s[threadIdx.x] - pv; // padded row start (4-aligned)
        g_dinv[i]   = rsqrtf((float)(v + 1));      // +1 self loop
    }
    // Fused prescale: x0 = fp16(dinv * emb); 16 threads/node, 4 floats each.
    __syncthreads();
    int node0 = b * 1024;
    uint2* xa2 = (uint2*)g_xa;
    for (int sweep = 0; sweep < 16; sweep++) {
        int node = node0 + sweep * 64 + (threadIdx.x >> 4);
        int q = threadIdx.x & 15;
        if (node < n) {
            float sc = g_dinv[node];
            float4 f = __ldg((const float4*)(emb + (size_t)node * DIM + q * 4));
            __half2 h0 = __floats2half2_rn(sc * f.x, sc * f.y);
            __half2 h1 = __floats2half2_rn(sc * f.z, sc * f.w);
            xa2[(size_t)node * 16 + q] = make_uint2(*(unsigned*)&h0, *(unsigned*)&h1);
        }
    }
}

// --- 3) counting-sort scatter: advances g_rowptr toward row end ------------
__global__ void k_scatter(const int* __restrict__ row, const int* __restrict__ col, int E) {
    int t = blockIdx.x * blockDim.x + threadIdx.x;
    int e = t * 4;
    if (e + 3 < E) {
        int4 r4 = __ldg((const int4*)(row + e));
        int4 c4 = __ldg((const int4*)(col + e));
        int p0 = atomicAdd(&g_rowptr[r4.x], 1);
        int p1 = atomicAdd(&g_rowptr[r4.y], 1);
        int p2 = atomicAdd(&g_rowptr[r4.z], 1);
        int p3 = atomicAdd(&g_rowptr[r4.w], 1);
        g_ecol[p0] = c4.x;
        g_ecol[p1] = c4.y;
        g_ecol[p2] = c4.z;
        g_ecol[p3] = c4.w;
    } else {
        for (int i = e; i < E; i++) {
            int p = atomicAdd(&g_rowptr[row[i]], 1);
            g_ecol[p] = col[i];
        }
    }
}

// --- streaming (evict-first) float4 store ----------------------------------
__device__ __forceinline__ void stcs_f4(float* p, float4 v) {
    asm volatile("st.global.cs.v4.f32 [%0], {%1, %2, %3, %4};"
                 :: "l"(p), "f"(v.x), "f"(v.y), "f"(v.z), "f"(v.w) : "memory");
}

// fp32 accumulate of a uint4 (8 fp16 values)
__device__ __forceinline__ void acc_u4(float4& a0, float4& a1, uint4 g) {
    float2 t;
    t = __half22float2(*(__half2*)&g.x); a0.x += t.x; a0.y += t.y;
    t = __half22float2(*(__half2*)&g.y); a0.z += t.x; a0.w += t.y;
    t = __half22float2(*(__half2*)&g.z); a1.x += t.x; a1.y += t.y;
    t = __half22float2(*(__half2*)&g.w); a1.z += t.x; a1.w += t.y;
}

// in-place fp16 pair add: a = a + b (componentwise half2); result reuses a's regs
__device__ __forceinline__ void hadd_ip(uint4& a, const uint4& b) {
    *(__half2*)&a.x = __hadd2(*(__half2*)&a.x, *(__half2*)&b.x);
    *(__half2*)&a.y = __hadd2(*(__half2*)&a.y, *(__half2*)&b.y);
    *(__half2*)&a.z = __hadd2(*(__half2*)&a.z, *(__half2*)&b.z);
    *(__half2*)&a.w = __hadd2(*(__half2*)&a.w, *(__half2*)&b.w);
}

// --- 4) SpMM on padded CSR: 4 rows/warp, 8 lanes/row, 16B per lane ---------
// Branch-free inner loop. Per 4 edges: 1 int4 index LDG + 4 gathers +
// 8 HADD2 (in-place pairwise fp16) + 8 CVT-pairs + 16 FADD.
// __launch_bounds__(256, 8) pins regs <= 32 so occupancy matches R14.
__global__ void __launch_bounds__(256, 8) k_spmm(
        const uint4* __restrict__ gx,
        float* __restrict__ out,           // stride 192 (permuted slot)
        uint4* __restrict__ xnext,         // 8 uint4 per row, or nullptr
        float* __restrict__ dup,           // stride 64 fp32, or nullptr
        int n) {
    int warpId = (blockIdx.x * blockDim.x + threadIdx.x) >> 5;
    int lane = threadIdx.x & 31;
    int slot = lane >> 3;                  // 0..3: row slot within warp
    int sub  = lane & 7;                   // 0..7: cols [sub*8, sub*8+8)
    int r = warpId * 4 + slot;
    bool rowok = (r < n);
    int rr = rowok ? r : 0;

    const char* gbase = (const char*)gx + ((unsigned)sub << 4);

    float4 a0, a1;
    {
        uint4 u = __ldg((const uint4*)(gbase + ((unsigned)rr << 7)));  // x[r]
        float2 t;
        t = __half22float2(*(__half2*)&u.x); a0 = make_float4(t.x, t.y, 0.f, 0.f);
        t = __half22float2(*(__half2*)&u.y); a0.z = t.x; a0.w = t.y;
        t = __half22float2(*(__half2*)&u.z); a1 = make_float4(t.x, t.y, 0.f, 0.f);
        t = __half22float2(*(__half2*)&u.w); a1.z = t.x; a1.w = t.y;
    }

    int len   = rowok ? __ldg(&g_cnt[rr]) : 0;
    int pecur = rowok ? __ldg(&g_rowptr[rr]) : 0;  // = start + len (post-scatter)
    int p     = pecur - len;                        // padded start (4-aligned)
    int pend  = p + ((len + 3) & ~3);               // padded end

    for (; p < pend; p += 4) {
        int4 c = __ldg((const int4*)&g_ecol[p]);
        uint4 g0 = __ldg((const uint4*)(gbase + ((unsigned)c.x << 7)));
        uint4 g1 = __ldg((const uint4*)(gbase + ((unsigned)c.y << 7)));
        uint4 g2 = __ldg((const uint4*)(gbase + ((unsigned)c.z << 7)));
        uint4 g3 = __ldg((const uint4*)(gbase + ((unsigned)c.w << 7)));
        hadd_ip(g0, g1);                   // g0 += g1 (fp16), frees g1
        hadd_ip(g2, g3);                   // g2 += g3 (fp16), frees g3
        acc_u4(a0, a1, g0);                // fp32 accumulate
        acc_u4(a0, a1, g2);
    }

    if (rowok) {
        float s = __ldg(&g_dinv[r]);
        float4 o0 = make_float4(s * a0.x, s * a0.y, s * a0.z, s * a0.w);
        float4 o1 = make_float4(s * a1.x, s * a1.y, s * a1.z, s * a1.w);
        float* orow = out + (size_t)r * 192 + sub * 8;
        stcs_f4(orow, o0);
        stcs_f4(orow + 4, o1);
        if (xnext) {
            __half2 q0 = __floats2half2_rn(s * o0.x, s * o0.y);
            __half2 q1 = __floats2half2_rn(s * o0.z, s * o0.w);
            __half2 q2 = __floats2half2_rn(s * o1.x, s * o1.y);
            __half2 q3 = __floats2half2_rn(s * o1.z, s * o1.w);
            xnext[(size_t)r * 8 + sub] =
                make_uint4(*(unsigned*)&q0, *(unsigned*)&q1,
                           *(unsigned*)&q2, *(unsigned*)&q3);
        }
        if (dup) {
            float* drow = dup + (size_t)r * DIM + sub * 8;
            stcs_f4(drow, o0);
            stcs_f4(drow + 4, o1);
        }
    }
}

// --- 5) cleanup: restore zeros for the next graph replay -------------------
__global__ void k_cleanup(int n) {
    int i = blockIdx.x * blockDim.x + threadIdx.x;
    if (i < n) g_cnt[i] = 0;
    if (i < 512) g_desc[i] = 0ULL;
}

// ---------------------------------------------------------------------------
extern "C" void kernel_launch(void* const* d_in, const int* in_sizes, int n_in,
                              void* d_out, int out_size) {
    const int* edge_index = (const int*)d_in[0];
    const float* emb      = (const float*)d_in[1];

    const int E = in_sizes[0] / 2;     // edge_index is (2, E) row-major
    const int n = in_sizes[1] / DIM;   // number of nodes

    const int* row = edge_index;
    const int* col = edge_index + E;

    float* out = (float*)d_out;
    // LAYER_PERM = (2,0,1): [0:64)=feats[2], [64:128)=feats[0], [128:192)=feats[1];
    // then feat (== feats[2]) again contiguously at n*192 if out_size covers it.
    float* f1 = out + 64;    // stride 192
    float* f2 = out + 128;   // stride 192
    float* f3 = out + 0;     // stride 192
    bool want_dup = ((long long)out_size >= (long long)n * 256);
    float* dup = want_dup ? (out + (size_t)n * 192) : nullptr;

    const int B = 256;
    const int q4 = (E + 3) / 4;
    const int epad = E + 3 * n + 16;       // upper bound on padded CSR size
    const int epad4 = (epad + 3) / 4;
    const int cnt_grid = (epad4 > q4 ? epad4 : q4);

    uint4* xa; cudaGetSymbolAddress((void**)&xa, g_xa);
    uint4* xb; cudaGetSymbolAddress((void**)&xb, g_xb);

    // g_cnt / g_desc are zero at entry (BSS on first call, k_cleanup after).
    k_count<<<(cnt_grid + B - 1) / B, B>>>(row, E, epad4, n);  // 0
    k_scan<<<(n + 1023) / 1024, 1024>>>(emb, n);               // 1
    k_scatter<<<(q4 + B - 1) / B, B>>>(row, col, E);           // 2

    // SpMM: 4 rows/warp -> 32 rows per 256-thread block
    const int spmm_blocks = (n + 31) / 32;
    k_spmm<<<spmm_blocks, B>>>(xa, f1, xb, nullptr, n);        // 3: layer 1
    k_spmm<<<spmm_blocks, B>>>(xb, f2, xa, nullptr, n);        // 4: layer 2
    k_spmm<<<spmm_blocks, B>>>(xa, f3, nullptr, dup, n);       // 5: layer 3

    k_cleanup<<<(n + B - 1) / B, B>>>(n);                      // 6
}